// round 12
// baseline (speedup 1.0000x reference)
#include <cuda_runtime.h>
#include <cstdint>

// ---------------------------------------------------------------------------
// out[i] = sum_{e: w_rows[e]==i} Param_W[w_params[e]] * x[w_cols[e]]
//          + Param_b[b_params[i]]
//
// N = 262144, E = 16.7M. Edge kernel is L1tex-wavefront bound; Param_W
// gathers are ~25% of wavefronts despite 100% L1 hits. R10 moves them to
// smem (random LDS = bank-degree ~4, far cheaper than ~22 divergent-line
// wavefronts/instr). The R3/R6 smem regression was the per-CTA staging
// (84MB @ 16384 CTAs); fixed here with 1024-thread CTAs -> 4096 CTAs, 21MB.
// Structure otherwise = R9 (scratch accumulator, epilogue adds bias+resets).
// ---------------------------------------------------------------------------

#define NMAX        262144
#define NPARAMS_MAX 2048
#define EDGE_BLOCK  1024

__device__ float g_acc[NMAX];   // zero at load; epilogue restores zero

// --- main edge scatter: 4 edges/thread, Param_W in smem -------------------
__global__ void __launch_bounds__(EDGE_BLOCK)
edge_scatter_smem_kernel(const float* __restrict__ x,
                         const float* __restrict__ Param_W,
                         const int4*  __restrict__ rows4,
                         const int4*  __restrict__ cols4,
                         const int4*  __restrict__ params4,
                         int E4, int nparams)
{
    __shared__ float sPW[NPARAMS_MAX];
    for (int i = threadIdx.x; i < nparams; i += EDGE_BLOCK)
        sPW[i] = Param_W[i];
    __syncthreads();

    int t = blockIdx.x * EDGE_BLOCK + threadIdx.x;
    if (t >= E4) return;

    int4 r = __ldcs(&rows4[t]);
    int4 c = __ldcs(&cols4[t]);
    int4 p = __ldcs(&params4[t]);

    float v0 = sPW[p.x] * __ldg(&x[c.x]);
    float v1 = sPW[p.y] * __ldg(&x[c.y]);
    float v2 = sPW[p.z] * __ldg(&x[c.z]);
    float v3 = sPW[p.w] * __ldg(&x[c.w]);

    atomicAdd(&g_acc[r.x], v0);
    atomicAdd(&g_acc[r.y], v1);
    atomicAdd(&g_acc[r.z], v2);
    atomicAdd(&g_acc[r.w], v3);
}

__global__ void edge_scatter_tail_kernel(const float* __restrict__ x,
                                         const float* __restrict__ Param_W,
                                         const int*   __restrict__ rows,
                                         const int*   __restrict__ cols,
                                         const int*   __restrict__ params,
                                         int start, int E)
{
    int e = start + blockIdx.x * blockDim.x + threadIdx.x;
    if (e < E) {
        float v = __ldg(&Param_W[params[e]]) * __ldg(&x[cols[e]]);
        atomicAdd(&g_acc[rows[e]], v);
    }
}

// --- epilogue: out = acc + bias; acc = 0 ----------------------------------
__global__ void __launch_bounds__(256)
epilogue_vec4_kernel(const float* __restrict__ Param_b,
                     const int4*  __restrict__ b_params4,
                     float4*      __restrict__ out4,
                     int N4)
{
    int i = blockIdx.x * blockDim.x + threadIdx.x;
    if (i < N4) {
        float4* acc4 = (float4*)&g_acc[i * 4];
        float4 a = *acc4;
        int4   b = b_params4[i];
        float4 o;
        o.x = a.x + __ldg(&Param_b[b.x]);
        o.y = a.y + __ldg(&Param_b[b.y]);
        o.z = a.z + __ldg(&Param_b[b.z]);
        o.w = a.w + __ldg(&Param_b[b.w]);
        out4[i] = o;
        *acc4 = make_float4(0.f, 0.f, 0.f, 0.f);
    }
}

__global__ void epilogue_tail_kernel(const float* __restrict__ Param_b,
                                     const int*   __restrict__ b_params,
                                     float*       __restrict__ out,
                                     int start, int N)
{
    int i = start + blockIdx.x * blockDim.x + threadIdx.x;
    if (i < N) {
        out[i] = g_acc[i] + __ldg(&Param_b[b_params[i]]);
        g_acc[i] = 0.f;
    }
}

// --- fallback for N > NMAX -------------------------------------------------
__global__ void bias_only_kernel(const float* __restrict__ Param_b,
                                 const int*   __restrict__ b_params,
                                 float*       __restrict__ out, int N)
{
    int i = blockIdx.x * blockDim.x + threadIdx.x;
    if (i < N) out[i] = __ldg(&Param_b[b_params[i]]);
}

__global__ void edge_scatter_direct_kernel(const float* __restrict__ x,
                                           const float* __restrict__ Param_W,
                                           const int*   __restrict__ rows,
                                           const int*   __restrict__ cols,
                                           const int*   __restrict__ params,
                                           float*       __restrict__ out,
                                           int E)
{
    int e = blockIdx.x * blockDim.x + threadIdx.x;
    if (e < E) {
        float v = __ldg(&Param_W[params[e]]) * __ldg(&x[cols[e]]);
        atomicAdd(&out[rows[e]], v);
    }
}

extern "C" void kernel_launch(void* const* d_in, const int* in_sizes, int n_in,
                              void* d_out, int out_size)
{
    const float* x        = (const float*)d_in[0];
    const float* Param_W  = (const float*)d_in[1];
    const float* Param_b  = (const float*)d_in[2];
    const int*   w_rows   = (const int*)  d_in[3];
    const int*   w_cols   = (const int*)  d_in[4];
    const int*   w_params = (const int*)  d_in[5];
    const int*   b_params = (const int*)  d_in[6];
    float*       out      = (float*)d_out;

    const int N       = out_size;     // 262144
    const int E       = in_sizes[3];  // 16777216
    const int nparams = in_sizes[1] < NPARAMS_MAX ? in_sizes[1] : NPARAMS_MAX;

    if (N > NMAX || in_sizes[1] > NPARAMS_MAX) {
        bias_only_kernel<<<(N + 255) / 256, 256>>>(Param_b, b_params, out, N);
        edge_scatter_direct_kernel<<<(E + 255) / 256, 256>>>(
            x, Param_W, w_rows, w_cols, w_params, out, E);
        return;
    }

    // 1) Edge scatter into g_acc (zero on entry). 1024-thr CTAs amortize the
    //    smem Param_W staging 4x vs 256-thr CTAs.
    int E4 = E / 4;
    if (E4 > 0) {
        int blocks = (E4 + EDGE_BLOCK - 1) / EDGE_BLOCK;   // 4096
        edge_scatter_smem_kernel<<<blocks, EDGE_BLOCK>>>(
            x, Param_W,
            (const int4*)w_rows, (const int4*)w_cols, (const int4*)w_params,
            E4, nparams);
    }
    int e_tail = E4 * 4;
    if (E - e_tail > 0) {
        edge_scatter_tail_kernel<<<1, 256>>>(
            x, Param_W, w_rows, w_cols, w_params, e_tail, E);
    }

    // 2) Epilogue: out = acc + gathered bias; acc reset to zero.
    int N4 = N / 4;
    if (N4 > 0) {
        int threads = 256;
        int blocks  = (N4 + threads - 1) / threads;
        epilogue_vec4_kernel<<<blocks, threads>>>(
            Param_b, (const int4*)b_params, (float4*)out, N4);
    }
    int n_tail = N4 * 4;
    if (N - n_tail > 0) {
        epilogue_tail_kernel<<<1, 256>>>(Param_b, b_params, out, n_tail, N);
    }
}